// round 16
// baseline (speedup 1.0000x reference)
#include <cuda_runtime.h>
#include <math.h>

#define EPSV 1e-06f
#define BLK 256
#define NWARP (BLK / 32)

struct Sim3 {
    float tx, ty, tz;
    float qx, qy, qz, qw;
    float s;
};

__device__ __forceinline__ Sim3 load_sim3(const float* __restrict__ p) {
    float4 a = *reinterpret_cast<const float4*>(p);
    float4 b = *reinterpret_cast<const float4*>(p + 4);
    Sim3 T;
    T.tx = a.x; T.ty = a.y; T.tz = a.z;
    T.qx = a.w; T.qy = b.x; T.qz = b.y; T.qw = b.z;
    T.s  = b.w;
    return T;
}

// fast atan2 for y >= 0; |error| ~1e-5 rad
__device__ __forceinline__ float fast_atan2_pos(float y, float x) {
    float ax = fabsf(x);
    float mn = fminf(ax, y);
    float mx = fmaxf(ax, y);
    float a  = __fdividef(mn, mx);
    float s  = a * a;
    float r  = fmaf(fmaf(fmaf(fmaf(0.0208351f, s, -0.0851330f), s,
                              0.1801410f), s, -0.3302995f), s, 0.9998660f) * a;
    if (y > ax)   r = 1.5707963268f - r;
    if (x < 0.0f) r = 3.1415926536f - r;
    return r;
}

__device__ __forceinline__ void quat_rotate(float qx, float qy, float qz, float qw,
                                            float vx, float vy, float vz,
                                            float& ox, float& oy, float& oz) {
    float ux = qy * vz - qz * vy;
    float uy = qz * vx - qx * vz;
    float uz = qx * vy - qy * vx;
    float wx = qy * uz - qz * uy;
    float wy = qz * ux - qx * uz;
    float wz = qx * uy - qy * ux;
    ox = vx + 2.0f * (qw * ux + wx);
    oy = vy + 2.0f * (qw * uy + wy);
    oz = vz + 2.0f * (qw * uz + wz);
}

// Fused sim3_mul(sim3_inv(T1), T2)
__device__ __forceinline__ Sim3 sim3_inv_mul(const Sim3& T1, const Sim3& T2) {
    float cx = -T1.qx, cy = -T1.qy, cz = -T1.qz, cw = T1.qw;
    float s_inv = __fdividef(1.0f, T1.s);

    float dx = T2.tx - T1.tx;
    float dy = T2.ty - T1.ty;
    float dz = T2.tz - T1.tz;
    float rx, ry, rz;
    quat_rotate(cx, cy, cz, cw, dx, dy, dz, rx, ry, rz);

    Sim3 R;
    R.tx = s_inv * rx; R.ty = s_inv * ry; R.tz = s_inv * rz;
    float x2 = T2.qx, y2 = T2.qy, z2 = T2.qz, w2 = T2.qw;
    R.qx = cw * x2 + cx * w2 + cy * z2 - cz * y2;
    R.qy = cw * y2 - cx * z2 + cy * w2 + cz * x2;
    R.qz = cw * z2 + cx * y2 - cy * x2 + cz * w2;
    R.qw = cw * w2 - cx * x2 - cy * y2 - cz * z2;
    R.s = s_inv * T2.s;
    return R;
}

__device__ __forceinline__ Sim3 sim3_mul(const Sim3& A, const Sim3& B) {
    Sim3 R;
    float rx, ry, rz;
    quat_rotate(A.qx, A.qy, A.qz, A.qw, B.tx, B.ty, B.tz, rx, ry, rz);
    R.tx = A.tx + A.s * rx;
    R.ty = A.ty + A.s * ry;
    R.tz = A.tz + A.s * rz;
    float x1 = A.qx, y1 = A.qy, z1 = A.qz, w1 = A.qw;
    float x2 = B.qx, y2 = B.qy, z2 = B.qz, w2 = B.qw;
    R.qx = w1 * x2 + x1 * w2 + y1 * z2 - z1 * y2;
    R.qy = w1 * y2 - x1 * z2 + y1 * w2 + z1 * x2;
    R.qz = w1 * z2 + x1 * y2 - y1 * x2 + z1 * w2;
    R.qw = w1 * w2 - x1 * x2 - y1 * y2 - z1 * z2;
    R.s = A.s * B.s;
    return R;
}

// out[7] = [tau(3), phi(3), sigma]  (R13 version — best measured)
__device__ __forceinline__ void sim3_log(const Sim3& T, float out[7]) {
    float qw = T.qw;
    float nv2 = T.qx * T.qx + T.qy * T.qy + T.qz * T.qz;
    float nv = (nv2 > 0.0f) ? nv2 * __frsqrt_rn(nv2) : 0.0f;

    // sin/cos of theta = 2*atan2(nv, qw) from the quaternion directly
    float qw2 = qw * qw;
    float n2 = nv2 + qw2;
    float inv_n2 = __fdividef(1.0f, n2);
    float cth = (qw2 - nv2) * inv_n2;
    float sth = 2.0f * qw * nv * inv_n2;

    float theta_r = 2.0f * fast_atan2_pos(nv, qw);
    bool small_r = nv < EPSV;
    float fac = small_r ? 2.0f : __fdividef(theta_r, nv);
    float px = fac * T.qx, py = fac * T.qy, pz = fac * T.qz;

    float sigma = __logf(T.s);
    float theta = fac * nv;   // == ||phi|| exactly

    bool sig_small = fabsf(sigma) < EPSV;
    bool th_small  = theta < EPSV;
    float sg = sig_small ? 1.0f : sigma;
    float th = th_small ? 1.0f : theta;

    float scale = T.s;        // exp(log(s)) == s
    float th2 = th * th;
    float sg2 = sg * sg;

    float C = sig_small ? 1.0f : __fdividef(scale - 1.0f, sg);

    float c      = th2 + sg2;
    float inv_c  = __fdividef(1.0f, c);
    float inv_th = __fdividef(1.0f, th);
    float inv_th2 = inv_th * inv_th;

    float a = scale * sth;
    float b = scale * cth;
    float A_g = (a * sg + (1.0f - b) * th) * inv_th * inv_c;
    float B_g = (C - ((b - 1.0f) * sg + a * th) * inv_c) * inv_th2;
    float A_ss = th_small ? 0.5f : (1.0f - cth) * inv_th2;
    float B_ss = th_small ? (1.0f / 6.0f) : (th - sth) * inv_th2 * inv_th;
    float A_ts = __fdividef((sg - 1.0f) * scale + 1.0f, sg2);
    float B_ts = __fdividef(scale * (sg2 - 2.0f * sg + 2.0f) - 2.0f, 2.0f * sg2 * sg);

    float A = sig_small ? A_ss : (th_small ? A_ts : A_g);
    float B = sig_small ? B_ss : (th_small ? B_ts : B_g);

    // W^-1 = x*I + y*Phi + z*Phi^2 (Phi^3 = -|phi|^2 Phi)
    float t2t = theta * theta;
    float P = C - t2t * B;
    float det2 = P * P + t2t * (A * A);
    float invC = __fdividef(1.0f, C);
    float invd = __fdividef(1.0f, det2);
    float y = -A * invd;
    float z = (A * A - P * B) * invC * invd;

    float tx = T.tx, ty = T.ty, tz = T.tz;
    float ux = py * tz - pz * ty;
    float uy = pz * tx - px * tz;
    float uz = px * ty - py * tx;
    float vx = py * uz - pz * uy;
    float vy = pz * ux - px * uz;
    float vz = px * uy - py * ux;

    out[0] = invC * tx + y * ux + z * vx;
    out[1] = invC * ty + y * uy + z * vy;
    out[2] = invC * tz + y * uz + z * vz;
    out[3] = px;
    out[4] = py;
    out[5] = pz;
    out[6] = sigma;
}

__global__ __launch_bounds__(BLK)
void pgo_kernel(const float* __restrict__ Twc,
                const float* __restrict__ Twc_prior_inv,
                const float* __restrict__ Todom_inv,
                const float* __restrict__ prior_weight,
                const float* __restrict__ odom_weight,
                const int*   __restrict__ edges,
                const float* __restrict__ T_lc,
                float* __restrict__ out,
                int n) {
    // warp-local staging: coalesced float4 weight loads + output stores
    __shared__ float s_pw[NWARP][224];    // 7 KB
    __shared__ float s_ow[NWARP][224];    // 7 KB
    __shared__ float s_out[NWARP][224];   // 7 KB

    unsigned tid = threadIdx.x;
    unsigned wid = tid >> 5;
    unsigned lane = tid & 31u;
    unsigned i = blockIdx.x * BLK + tid;

    bool valid = i < (unsigned)n;
    unsigned ic = valid ? i : (unsigned)(n - 1);   // clamp for safe loads
    unsigned warp_row0 = blockIdx.x * BLK + wid * 32u;
    bool full_warp = (warp_row0 + 31u) < (unsigned)n;

    // ---- stage weight loads FIRST: coalesced LDG.128 -> smem, in flight
    //      behind the gathers, zero register cost ----
    if (full_warp) {
        const float4* srcp = reinterpret_cast<const float4*>(prior_weight + 7u * warp_row0);
        const float4* srco = reinterpret_cast<const float4*>(odom_weight + 7u * warp_row0);
        float4* dp = reinterpret_cast<float4*>(s_pw[wid]);
        float4* dw = reinterpret_cast<float4*>(s_ow[wid]);
        #pragma unroll
        for (unsigned j = lane; j < 56u; j += 32u) { dp[j] = srcp[j]; dw[j] = srco[j]; }
    }

    // issue the random gather early so its latency overlaps the math below
    int2 e = *reinterpret_cast<const int2*>(edges + 2u * ic);
    Sim3 Ta = load_sim3(Twc + 8u * (unsigned)e.x);
    Sim3 Tb = load_sim3(Twc + 8u * (unsigned)e.y);
    Sim3 Tl = load_sim3(T_lc + 8u * ic);

    Sim3 Ti  = load_sim3(Twc + 8u * ic);
    Sim3 Tj  = load_sim3(Twc + 8u * (ic + 1u));
    Sim3 delta = sim3_inv_mul(Ti, Tj);

    float r_prior[7], r_odom[7], r_lc[7];

    Sim3 Tp = load_sim3(Twc_prior_inv + 8u * ic);
    sim3_log(sim3_mul(delta, Tp), r_prior);

    Sim3 To = load_sim3(Todom_inv + 8u * ic);
    sim3_log(sim3_mul(delta, To), r_odom);

    Sim3 delta_lc = sim3_inv_mul(Ta, Tb);
    sim3_log(sim3_mul(delta_lc, Tl), r_lc);

    if (full_warp) {
        __syncwarp();
        // conflict-free LDS reads (7*lane+k, gcd(7,32)=1), fma, stage stores
        const float* pw = s_pw[wid] + 7u * lane;
        const float* ow = s_ow[wid] + 7u * lane;
        float* so = s_out[wid] + 7u * lane;
        #pragma unroll
        for (int k = 0; k < 7; k++) {
            so[k] = fmaf(r_prior[k], pw[k], fmaf(r_odom[k], ow[k], r_lc[k]));
        }
        __syncwarp();

        float4* dst = reinterpret_cast<float4*>(out + 7u * warp_row0);
        const float4* src = reinterpret_cast<const float4*>(s_out[wid]);
        #pragma unroll
        for (unsigned j = lane; j < 56u; j += 32u) dst[j] = src[j];
    } else if (valid) {
        // tail warp: scalar path
        const float* pw = prior_weight + 7u * i;
        const float* ow = odom_weight + 7u * i;
        float* o = out + 7u * i;
        #pragma unroll
        for (int k = 0; k < 7; k++) {
            o[k] = fmaf(r_prior[k], pw[k], fmaf(r_odom[k], ow[k], r_lc[k]));
        }
    }
}

extern "C" void kernel_launch(void* const* d_in, const int* in_sizes, int n_in,
                              void* d_out, int out_size) {
    const float* Twc           = (const float*)d_in[0];
    const float* Twc_prior_inv = (const float*)d_in[1];
    const float* Todom_inv     = (const float*)d_in[2];
    const float* prior_weight  = (const float*)d_in[3];
    const float* odom_weight   = (const float*)d_in[4];
    const int*   edges         = (const int*)d_in[5];
    const float* T_lc          = (const float*)d_in[6];
    float* out = (float*)d_out;

    int n = out_size / 7;

    int blocks = (n + BLK - 1) / BLK;
    pgo_kernel<<<blocks, BLK>>>(Twc, Twc_prior_inv, Todom_inv,
                                prior_weight, odom_weight, edges, T_lc,
                                out, n);
}

// round 17
// speedup vs baseline: 1.1106x; 1.1106x over previous
#include <cuda_runtime.h>
#include <math.h>

#define EPSV 1e-06f
#define BLK 256
#define NSM 152
#define CTAS_PER_SM 4

struct Sim3 {
    float tx, ty, tz;
    float qx, qy, qz, qw;
    float s;
};

__device__ __forceinline__ Sim3 load_sim3(const float* __restrict__ p) {
    float4 a = *reinterpret_cast<const float4*>(p);
    float4 b = *reinterpret_cast<const float4*>(p + 4);
    Sim3 T;
    T.tx = a.x; T.ty = a.y; T.tz = a.z;
    T.qx = a.w; T.qy = b.x; T.qz = b.y; T.qw = b.z;
    T.s  = b.w;
    return T;
}

// fast atan2 for y >= 0; |error| ~1e-5 rad
__device__ __forceinline__ float fast_atan2_pos(float y, float x) {
    float ax = fabsf(x);
    float mn = fminf(ax, y);
    float mx = fmaxf(ax, y);
    float a  = __fdividef(mn, mx);
    float s  = a * a;
    float r  = fmaf(fmaf(fmaf(fmaf(0.0208351f, s, -0.0851330f), s,
                              0.1801410f), s, -0.3302995f), s, 0.9998660f) * a;
    if (y > ax)   r = 1.5707963268f - r;
    if (x < 0.0f) r = 3.1415926536f - r;
    return r;
}

__device__ __forceinline__ void quat_rotate(float qx, float qy, float qz, float qw,
                                            float vx, float vy, float vz,
                                            float& ox, float& oy, float& oz) {
    float ux = qy * vz - qz * vy;
    float uy = qz * vx - qx * vz;
    float uz = qx * vy - qy * vx;
    float wx = qy * uz - qz * uy;
    float wy = qz * ux - qx * uz;
    float wz = qx * uy - qy * ux;
    ox = vx + 2.0f * (qw * ux + wx);
    oy = vy + 2.0f * (qw * uy + wy);
    oz = vz + 2.0f * (qw * uz + wz);
}

// Fused sim3_mul(sim3_inv(T1), T2)
__device__ __forceinline__ Sim3 sim3_inv_mul(const Sim3& T1, const Sim3& T2) {
    float cx = -T1.qx, cy = -T1.qy, cz = -T1.qz, cw = T1.qw;
    float s_inv = __fdividef(1.0f, T1.s);

    float dx = T2.tx - T1.tx;
    float dy = T2.ty - T1.ty;
    float dz = T2.tz - T1.tz;
    float rx, ry, rz;
    quat_rotate(cx, cy, cz, cw, dx, dy, dz, rx, ry, rz);

    Sim3 R;
    R.tx = s_inv * rx; R.ty = s_inv * ry; R.tz = s_inv * rz;
    float x2 = T2.qx, y2 = T2.qy, z2 = T2.qz, w2 = T2.qw;
    R.qx = cw * x2 + cx * w2 + cy * z2 - cz * y2;
    R.qy = cw * y2 - cx * z2 + cy * w2 + cz * x2;
    R.qz = cw * z2 + cx * y2 - cy * x2 + cz * w2;
    R.qw = cw * w2 - cx * x2 - cy * y2 - cz * z2;
    R.s = s_inv * T2.s;
    return R;
}

__device__ __forceinline__ Sim3 sim3_mul(const Sim3& A, const Sim3& B) {
    Sim3 R;
    float rx, ry, rz;
    quat_rotate(A.qx, A.qy, A.qz, A.qw, B.tx, B.ty, B.tz, rx, ry, rz);
    R.tx = A.tx + A.s * rx;
    R.ty = A.ty + A.s * ry;
    R.tz = A.tz + A.s * rz;
    float x1 = A.qx, y1 = A.qy, z1 = A.qz, w1 = A.qw;
    float x2 = B.qx, y2 = B.qy, z2 = B.qz, w2 = B.qw;
    R.qx = w1 * x2 + x1 * w2 + y1 * z2 - z1 * y2;
    R.qy = w1 * y2 - x1 * z2 + y1 * w2 + z1 * x2;
    R.qz = w1 * z2 + x1 * y2 - y1 * x2 + z1 * w2;
    R.qw = w1 * w2 - x1 * x2 - y1 * y2 - z1 * z2;
    R.s = A.s * B.s;
    return R;
}

// out[7] = [tau(3), phi(3), sigma]  (R13 version — best measured)
__device__ __forceinline__ void sim3_log(const Sim3& T, float out[7]) {
    float qw = T.qw;
    float nv2 = T.qx * T.qx + T.qy * T.qy + T.qz * T.qz;
    float nv = (nv2 > 0.0f) ? nv2 * __frsqrt_rn(nv2) : 0.0f;

    // sin/cos of theta = 2*atan2(nv, qw) from the quaternion directly
    float qw2 = qw * qw;
    float n2 = nv2 + qw2;
    float inv_n2 = __fdividef(1.0f, n2);
    float cth = (qw2 - nv2) * inv_n2;
    float sth = 2.0f * qw * nv * inv_n2;

    float theta_r = 2.0f * fast_atan2_pos(nv, qw);
    bool small_r = nv < EPSV;
    float fac = small_r ? 2.0f : __fdividef(theta_r, nv);
    float px = fac * T.qx, py = fac * T.qy, pz = fac * T.qz;

    float sigma = __logf(T.s);
    float theta = fac * nv;   // == ||phi|| exactly

    bool sig_small = fabsf(sigma) < EPSV;
    bool th_small  = theta < EPSV;
    float sg = sig_small ? 1.0f : sigma;
    float th = th_small ? 1.0f : theta;

    float scale = T.s;        // exp(log(s)) == s
    float th2 = th * th;
    float sg2 = sg * sg;

    float C = sig_small ? 1.0f : __fdividef(scale - 1.0f, sg);

    float c      = th2 + sg2;
    float inv_c  = __fdividef(1.0f, c);
    float inv_th = __fdividef(1.0f, th);
    float inv_th2 = inv_th * inv_th;

    float a = scale * sth;
    float b = scale * cth;
    float A_g = (a * sg + (1.0f - b) * th) * inv_th * inv_c;
    float B_g = (C - ((b - 1.0f) * sg + a * th) * inv_c) * inv_th2;
    float A_ss = th_small ? 0.5f : (1.0f - cth) * inv_th2;
    float B_ss = th_small ? (1.0f / 6.0f) : (th - sth) * inv_th2 * inv_th;
    float A_ts = __fdividef((sg - 1.0f) * scale + 1.0f, sg2);
    float B_ts = __fdividef(scale * (sg2 - 2.0f * sg + 2.0f) - 2.0f, 2.0f * sg2 * sg);

    float A = sig_small ? A_ss : (th_small ? A_ts : A_g);
    float B = sig_small ? B_ss : (th_small ? B_ts : B_g);

    // W^-1 = x*I + y*Phi + z*Phi^2 (Phi^3 = -|phi|^2 Phi)
    float t2t = theta * theta;
    float P = C - t2t * B;
    float det2 = P * P + t2t * (A * A);
    float invC = __fdividef(1.0f, C);
    float invd = __fdividef(1.0f, det2);
    float y = -A * invd;
    float z = (A * A - P * B) * invC * invd;

    float tx = T.tx, ty = T.ty, tz = T.tz;
    float ux = py * tz - pz * ty;
    float uy = pz * tx - px * tz;
    float uz = px * ty - py * tx;
    float vx = py * uz - pz * uy;
    float vy = pz * ux - px * uz;
    float vz = px * uy - py * ux;

    out[0] = invC * tx + y * ux + z * vx;
    out[1] = invC * ty + y * uy + z * vy;
    out[2] = invC * tz + y * uz + z * vz;
    out[3] = px;
    out[4] = py;
    out[5] = pz;
    out[6] = sigma;
}

__global__ __launch_bounds__(BLK)
void pgo_kernel(const float* __restrict__ Twc,
                const float* __restrict__ Twc_prior_inv,
                const float* __restrict__ Todom_inv,
                const float* __restrict__ prior_weight,
                const float* __restrict__ odom_weight,
                const int*   __restrict__ edges,
                const float* __restrict__ T_lc,
                float* __restrict__ out,
                int n) {
    unsigned stride = gridDim.x * BLK;

    // persistent grid-stride: one wave, balanced work, loads of the next
    // row overlap the FMA tail of the previous row within each warp
    for (unsigned i = blockIdx.x * BLK + threadIdx.x; i < (unsigned)n; i += stride) {
        // issue the random gather first so its latency overlaps the math below
        int2 e = *reinterpret_cast<const int2*>(edges + 2u * i);
        Sim3 Ta = load_sim3(Twc + 8u * (unsigned)e.x);
        Sim3 Tb = load_sim3(Twc + 8u * (unsigned)e.y);
        Sim3 Tl = load_sim3(T_lc + 8u * i);

        Sim3 Ti  = load_sim3(Twc + 8u * i);
        Sim3 Tj  = load_sim3(Twc + 8u * (i + 1u));
        Sim3 delta = sim3_inv_mul(Ti, Tj);

        float r_prior[7], r_odom[7], r_lc[7];

        Sim3 Tp = load_sim3(Twc_prior_inv + 8u * i);
        sim3_log(sim3_mul(delta, Tp), r_prior);

        Sim3 To = load_sim3(Todom_inv + 8u * i);
        sim3_log(sim3_mul(delta, To), r_odom);

        Sim3 delta_lc = sim3_inv_mul(Ta, Tb);
        sim3_log(sim3_mul(delta_lc, Tl), r_lc);

        const float* pw = prior_weight + 7u * i;
        const float* ow = odom_weight + 7u * i;
        float* o = out + 7u * i;
        #pragma unroll
        for (int k = 0; k < 7; k++) {
            o[k] = fmaf(r_prior[k], pw[k], fmaf(r_odom[k], ow[k], r_lc[k]));
        }
    }
}

extern "C" void kernel_launch(void* const* d_in, const int* in_sizes, int n_in,
                              void* d_out, int out_size) {
    const float* Twc           = (const float*)d_in[0];
    const float* Twc_prior_inv = (const float*)d_in[1];
    const float* Todom_inv     = (const float*)d_in[2];
    const float* prior_weight  = (const float*)d_in[3];
    const float* odom_weight   = (const float*)d_in[4];
    const int*   edges         = (const int*)d_in[5];
    const float* T_lc          = (const float*)d_in[6];
    float* out = (float*)d_out;

    int n = out_size / 7;

    int max_blocks = NSM * CTAS_PER_SM;                 // one full wave
    int need = (n + BLK - 1) / BLK;
    int blocks = need < max_blocks ? need : max_blocks;
    pgo_kernel<<<blocks, BLK>>>(Twc, Twc_prior_inv, Todom_inv,
                                prior_weight, odom_weight, edges, T_lc,
                                out, n);
}